// round 1
// baseline (speedup 1.0000x reference)
#include <cuda_runtime.h>
#include <cuda_bf16.h>

#define B_TOTAL        65536
#define N_K            64
#define ROW_FLOATS     (N_K * 3)          // 192 floats per row per tensor
#define DEGREE         3
#define SAMPLES        20
#define ROWS_PER_BLOCK 16
#define THREADS        (ROWS_PER_BLOCK * SAMPLES)  // 320
#define NBLOCKS        (B_TOTAL / ROWS_PER_BLOCK)  // 4096

__device__ double g_partials[NBLOCKS];

// Evaluate one De Boor sample (x,y) for the row data laid out as
// rowd[3*i] = knot_i, rowd[3*i+1] = cx_i, rowd[3*i+2] = cy_i.
__device__ __forceinline__ void deboor_sample(const float* __restrict__ rowd,
                                              int j, float& ox, float& oy)
{
    const float high = rowd[3 * 60];                 // knots[60] == kf[64]
    const float t = ((float)j / 19.0f) * high;       // low == 0

    // s = 3 + #{i in [0,60) : knots[i] <= t}  (binary search, upper bound)
    int lo = 0, hi = 60;
    while (lo < hi) {
        int mid = (lo + hi) >> 1;
        if (rowd[3 * mid] <= t) lo = mid + 1; else hi = mid;
    }
    const int i0 = lo;                               // s - 3, in [0, 60]

    // kf[i0 + m] for m = 0..6 ;  kf[i] = (i < 4) ? 0 : knots[i-4]
    float kfv[7];
#pragma unroll
    for (int m = 0; m < 7; m++) {
        int ii = i0 + m;
        kfv[m] = (ii < 4) ? 0.0f : rowd[3 * (ii - 4)];
    }

    float px[4], py[4];
#pragma unroll
    for (int k = 0; k < 4; k++) {
        px[k] = rowd[3 * (i0 + k) + 1];
        py[k] = rowd[3 * (i0 + k) + 2];
    }

    // De Boor: l = 1..3, k descending so old p[k-1] is read.
#pragma unroll
    for (int l = 1; l <= DEGREE; l++) {
#pragma unroll
        for (int k = 3; k >= 1; k--) {
            if (k < l) break;
            float ki = kfv[k];
            float kj = kfv[k + 4 - l];
            float denom = kj - ki;
            float alpha = (denom != 0.0f) ? (t - ki) / denom : 0.0f;
            px[k] = (1.0f - alpha) * px[k - 1] + alpha * px[k];
            py[k] = (1.0f - alpha) * py[k - 1] + alpha * py[k];
        }
    }
    // homogeneous weight is exactly 1 (affine combos of 1) -> no division needed
    ox = px[3];
    oy = py[3];
}

__global__ __launch_bounds__(THREADS)
void bspline_loss_main(const float* __restrict__ pred,
                       const float* __restrict__ tru)
{
    __shared__ float smem[2][ROWS_PER_BLOCK][ROW_FLOATS];

    // Cooperative coalesced load: 16 rows x 192 floats = 768 float4 per tensor.
    {
        const size_t base = (size_t)blockIdx.x * ROWS_PER_BLOCK * ROW_FLOATS;
        const float4* gp = reinterpret_cast<const float4*>(pred + base);
        const float4* gt = reinterpret_cast<const float4*>(tru + base);
        float4* sp = reinterpret_cast<float4*>(&smem[0][0][0]);
        float4* st = reinterpret_cast<float4*>(&smem[1][0][0]);
        const int n4 = ROWS_PER_BLOCK * ROW_FLOATS / 4;   // 768
        for (int i = threadIdx.x; i < n4; i += THREADS) {
            sp[i] = gp[i];
            st[i] = gt[i];
        }
    }
    __syncthreads();

    const int row = threadIdx.x / SAMPLES;
    const int j   = threadIdx.x % SAMPLES;

    float pxv, pyv, txv, tyv;
    deboor_sample(&smem[0][row][0], j, pxv, pyv);
    deboor_sample(&smem[1][row][0], j, txv, tyv);

    float dx = pxv - txv;
    float dy = pyv - tyv;
    float val = dx * dx + dy * dy;

    // Block reduction: 10 full warps.
#pragma unroll
    for (int o = 16; o > 0; o >>= 1)
        val += __shfl_down_sync(0xFFFFFFFFu, val, o);

    __shared__ float warpsum[THREADS / 32];
    const int wid  = threadIdx.x >> 5;
    const int lane = threadIdx.x & 31;
    if (lane == 0) warpsum[wid] = val;
    __syncthreads();

    if (threadIdx.x == 0) {
        double tot = 0.0;
#pragma unroll
        for (int w = 0; w < THREADS / 32; w++) tot += (double)warpsum[w];
        g_partials[blockIdx.x] = tot;
    }
}

__global__ __launch_bounds__(256)
void bspline_loss_finalize(float* __restrict__ out)
{
    __shared__ double sh[256];
    double s = 0.0;
    for (int i = threadIdx.x; i < NBLOCKS; i += 256) s += g_partials[i];
    sh[threadIdx.x] = s;
    __syncthreads();
#pragma unroll
    for (int st = 128; st > 0; st >>= 1) {
        if (threadIdx.x < st) sh[threadIdx.x] += sh[threadIdx.x + st];
        __syncthreads();
    }
    if (threadIdx.x == 0)
        out[0] = (float)(sh[0] / (double)((long long)B_TOTAL * SAMPLES));
}

extern "C" void kernel_launch(void* const* d_in, const int* in_sizes, int n_in,
                              void* d_out, int out_size)
{
    const float* pred = (const float*)d_in[0];
    const float* tru  = (const float*)d_in[1];
    float* out = (float*)d_out;

    bspline_loss_main<<<NBLOCKS, THREADS>>>(pred, tru);
    bspline_loss_finalize<<<1, 256>>>(out);
}

// round 2
// speedup vs baseline: 1.2767x; 1.2767x over previous
#include <cuda_runtime.h>
#include <cuda_bf16.h>

#define B_TOTAL        65536
#define N_K            64
#define ROW_FLOATS     (N_K * 3)          // 192 floats per row per tensor
#define DEGREE         3
#define SAMPLES        20
#define ROWS_PER_BLOCK 8
#define THREADS        (ROWS_PER_BLOCK * SAMPLES)  // 160
#define NBLOCKS        (B_TOTAL / ROWS_PER_BLOCK)  // 8192

__device__ double        g_sum;     // zero-init at module load; reset by last block
__device__ unsigned int  g_count;   // zero-init at module load; reset by last block

// Branchless "count of knots <= t" over knots[0..59], knots at rowd[3*i].
// 6 fixed iterations; pred & true interleaved for overlapped LDS chains.
__device__ __forceinline__ void dual_search(const float* __restrict__ ra, float ta,
                                            const float* __restrict__ rb, float tb,
                                            int& i0a, int& i0b)
{
    int a = 0, b = 0;
#pragma unroll
    for (int step = 32; step > 0; step >>= 1) {
        int ca = a + step;
        int cb = b + step;
        if (ca <= 60 && ra[3 * (ca - 1)] <= ta) a = ca;
        if (cb <= 60 && rb[3 * (cb - 1)] <= tb) b = cb;
    }
    i0a = a;
    i0b = b;
}

// De Boor sample given interval index i0 (= s-3).
__device__ __forceinline__ void deboor_eval(const float* __restrict__ rowd,
                                            float t, int i0,
                                            float& ox, float& oy)
{
    // kf[i0 + m], m=0..6 ; kf[i] = (i < 4) ? 0 : knots[i-4]
    float kfv[7];
#pragma unroll
    for (int m = 0; m < 7; m++) {
        int ii = i0 + m;
        kfv[m] = (ii < 4) ? 0.0f : rowd[3 * (ii - 4)];
    }

    float px[4], py[4];
#pragma unroll
    for (int k = 0; k < 4; k++) {
        px[k] = rowd[3 * (i0 + k) + 1];
        py[k] = rowd[3 * (i0 + k) + 2];
    }

#pragma unroll
    for (int l = 1; l <= DEGREE; l++) {
#pragma unroll
        for (int k = 3; k >= 1; k--) {
            if (k < l) break;
            float ki = kfv[k];
            float kj = kfv[k + 4 - l];
            float denom = kj - ki;
            float alpha = (denom != 0.0f) ? (t - ki) / denom : 0.0f;
            px[k] = (1.0f - alpha) * px[k - 1] + alpha * px[k];
            py[k] = (1.0f - alpha) * py[k - 1] + alpha * py[k];
        }
    }
    // homogeneous weight stays exactly 1 -> no division
    ox = px[3];
    oy = py[3];
}

__global__ __launch_bounds__(THREADS)
void bspline_loss_fused(const float* __restrict__ pred,
                        const float* __restrict__ tru,
                        float* __restrict__ out)
{
    __shared__ float smem[2][ROWS_PER_BLOCK][ROW_FLOATS];

    // Coalesced cooperative load: 8 rows x 192 floats = 384 float4 per tensor.
    {
        const size_t base = (size_t)blockIdx.x * ROWS_PER_BLOCK * ROW_FLOATS;
        const float4* gp = reinterpret_cast<const float4*>(pred + base);
        const float4* gt = reinterpret_cast<const float4*>(tru + base);
        float4* sp = reinterpret_cast<float4*>(&smem[0][0][0]);
        float4* st = reinterpret_cast<float4*>(&smem[1][0][0]);
        const int n4 = ROWS_PER_BLOCK * ROW_FLOATS / 4;   // 384
#pragma unroll
        for (int i = threadIdx.x; i < n4; i += THREADS) {
            sp[i] = gp[i];
            st[i] = gt[i];
        }
    }
    __syncthreads();

    const int row = threadIdx.x / SAMPLES;
    const int j   = threadIdx.x % SAMPLES;

    const float* rp = &smem[0][row][0];
    const float* rt = &smem[1][row][0];

    const float tp = ((float)j / 19.0f) * rp[3 * 60];  // low == 0
    const float tt = ((float)j / 19.0f) * rt[3 * 60];

    int i0p, i0t;
    dual_search(rp, tp, rt, tt, i0p, i0t);

    float pxv, pyv, txv, tyv;
    deboor_eval(rp, tp, i0p, pxv, pyv);
    deboor_eval(rt, tt, i0t, txv, tyv);

    float dx = pxv - txv;
    float dy = pyv - tyv;
    float val = dx * dx + dy * dy;

    // Warp reduce (5 full warps).
#pragma unroll
    for (int o = 16; o > 0; o >>= 1)
        val += __shfl_down_sync(0xFFFFFFFFu, val, o);

    __shared__ float warpsum[THREADS / 32];
    const int wid  = threadIdx.x >> 5;
    const int lane = threadIdx.x & 31;
    if (lane == 0) warpsum[wid] = val;
    __syncthreads();

    if (threadIdx.x == 0) {
        double tot = 0.0;
#pragma unroll
        for (int w = 0; w < THREADS / 32; w++) tot += (double)warpsum[w];
        atomicAdd(&g_sum, tot);
        __threadfence();
        unsigned int ticket = atomicAdd(&g_count, 1u);
        if (ticket == NBLOCKS - 1) {
            // Last block: publish result and reset state for next replay.
            out[0] = (float)(g_sum / (double)((long long)B_TOTAL * SAMPLES));
            g_sum = 0.0;
            __threadfence();
            g_count = 0u;
        }
    }
}

extern "C" void kernel_launch(void* const* d_in, const int* in_sizes, int n_in,
                              void* d_out, int out_size)
{
    const float* pred = (const float*)d_in[0];
    const float* tru  = (const float*)d_in[1];
    float* out = (float*)d_out;

    bspline_loss_fused<<<NBLOCKS, THREADS>>>(pred, tru, out);
}